// round 2
// baseline (speedup 1.0000x reference)
#include <cuda_runtime.h>
#include <cstdint>

// ---------------------------------------------------------------------------
// EncoderGRU: bidirectional GRU, SEQ=4096, HIDDEN=EMBED=1024.
//
//   Phase 1: prep tokens (+ zero h ring buffers, reset step flags).
//   Phase 2: GI[t] = w_ih @ emb[tok[t]] + b_ih  -- fp32 SIMT GEMM (4098x3072x1024)
//   Phase 3: persistent kernel, 128 CTAs (64 fwd / 64 bwd), each CTA owns 16
//            hidden units (48 w_hh rows in smem). Per step: 48 dot products
//            against broadcast h, pointwise GRU update. Synchronization is a
//            per-direction flag array (monotonic step counters) -- NO atomics,
//            fwd and bwd fully decoupled.
// ---------------------------------------------------------------------------

#define VOCAB   50257
#define HID     1024
#define SEQ     4096
#define NROWS   (SEQ + 2)       // 4098: +SOS row, +EOS row
#define GATES   3072

#define NCTA    128             // persistent grid (1 CTA/SM)
#define UNITS   16              // hidden units per CTA (64 CTAs/dir * 16 = 1024)
#define RPC     48              // weight rows per CTA (3 gates * 16 units)
#define GT      256             // threads in recurrent kernel
#define RPW     6               // rows per warp (8 warps * 6 = 48)

// ---- global scratch (allocation-free: __device__ globals) ----
__device__ __align__(16) int   g_tokens[NROWS];
__device__ __align__(16) float g_GI[(size_t)NROWS * GATES];     // ~50 MB
__device__ __align__(16) float g_h[2][2][HID];                  // [dir][buf][unit]
__device__ __align__(16) int   g_flags[2][64];                  // [dir][cta]: last step written

// ---------------------------------------------------------------------------
// Phase 1: token prep + dtype detection + state reset (graph-replay safe)
// ---------------------------------------------------------------------------
__global__ void prep_tokens_kernel(const void* __restrict__ tok_raw) {
    __shared__ int mode64;
    if (threadIdx.x == 0) {
        // Genuine int64 tokens: every value < VOCAB (high word 0).
        // int32 data misread as int64: some 64-bit word >= VOCAB w.h.p.
        const unsigned long long* p = (const unsigned long long*)tok_raw;
        int m = 1;
        #pragma unroll
        for (int i = 0; i < 8; i++)
            if (p[i] >= (unsigned long long)VOCAB) m = 0;
        mode64 = m;
    }
    __syncthreads();
    int idx    = blockIdx.x * blockDim.x + threadIdx.x;
    int stride = blockDim.x * gridDim.x;
    for (int i = idx; i < SEQ; i += stride) {
        int t = mode64 ? (int)((const long long*)tok_raw)[i]
                       : ((const int*)tok_raw)[i];
        g_tokens[i] = t;
    }
    // reset recurrent state (fresh every launch / graph replay)
    if (idx < 2 * 2 * HID) ((float*)g_h)[idx] = 0.f;
    if (idx < 2 * 64)      ((int*)g_flags)[idx] = -1;
    if (blockIdx.x == 0 && threadIdx.x == 0) {
        g_tokens[SEQ]     = 0;  // SOS
        g_tokens[SEQ + 1] = 1;  // EOS
    }
}

// ---------------------------------------------------------------------------
// Phase 2: GI GEMM.  C[m][n] = sum_k emb[tok[m]][k] * w_ih[n][k] + b_ih[n]
// BM=BN=128, BK=8, 256 threads, 8x8 microtile per thread.
// ---------------------------------------------------------------------------
#define BM 128
#define BN 128
#define BK 8

__global__ void __launch_bounds__(256) gi_gemm_kernel(
    const float* __restrict__ emb,
    const float* __restrict__ w_ih,
    const float* __restrict__ b_ih) {

    __shared__ float As[BK][BM];
    __shared__ float Bs[BK][BN];

    const int tid  = threadIdx.x;
    const int m0   = blockIdx.y * BM;
    const int n0   = blockIdx.x * BN;
    const int lrow = tid >> 1;          // 0..127
    const int lk   = (tid & 1) * 4;     // 0 or 4
    const int tx   = tid & 15;
    const int ty   = tid >> 4;

    const int m = m0 + lrow;
    const float* arow_ptr = nullptr;
    if (m < NROWS) arow_ptr = emb + (size_t)g_tokens[m] * HID;
    const float* brow_ptr = w_ih + (size_t)(n0 + lrow) * HID;

    float acc[8][8];
    #pragma unroll
    for (int i = 0; i < 8; i++)
        #pragma unroll
        for (int j = 0; j < 8; j++) acc[i][j] = 0.f;

    for (int k0 = 0; k0 < HID; k0 += BK) {
        float4 a4 = make_float4(0.f, 0.f, 0.f, 0.f);
        if (arow_ptr) a4 = *(const float4*)(arow_ptr + k0 + lk);
        float4 b4 = *(const float4*)(brow_ptr + k0 + lk);
        As[lk + 0][lrow] = a4.x; As[lk + 1][lrow] = a4.y;
        As[lk + 2][lrow] = a4.z; As[lk + 3][lrow] = a4.w;
        Bs[lk + 0][lrow] = b4.x; Bs[lk + 1][lrow] = b4.y;
        Bs[lk + 2][lrow] = b4.z; Bs[lk + 3][lrow] = b4.w;
        __syncthreads();

        #pragma unroll
        for (int kk = 0; kk < BK; kk++) {
            float ra[8], rb[8];
            *(float4*)&ra[0] = *(const float4*)&As[kk][ty * 8];
            *(float4*)&ra[4] = *(const float4*)&As[kk][ty * 8 + 4];
            *(float4*)&rb[0] = *(const float4*)&Bs[kk][tx * 8];
            *(float4*)&rb[4] = *(const float4*)&Bs[kk][tx * 8 + 4];
            #pragma unroll
            for (int i = 0; i < 8; i++)
                #pragma unroll
                for (int j = 0; j < 8; j++)
                    acc[i][j] += ra[i] * rb[j];
        }
        __syncthreads();
    }

    float bias[8];
    *(float4*)&bias[0] = *(const float4*)(b_ih + n0 + tx * 8);
    *(float4*)&bias[4] = *(const float4*)(b_ih + n0 + tx * 8 + 4);

    #pragma unroll
    for (int i = 0; i < 8; i++) {
        int mm = m0 + ty * 8 + i;
        if (mm < NROWS) {
            float* gp = g_GI + (size_t)mm * GATES + n0 + tx * 8;
            float4 v0 = make_float4(acc[i][0] + bias[0], acc[i][1] + bias[1],
                                    acc[i][2] + bias[2], acc[i][3] + bias[3]);
            float4 v1 = make_float4(acc[i][4] + bias[4], acc[i][5] + bias[5],
                                    acc[i][6] + bias[6], acc[i][7] + bias[7]);
            *(float4*)gp       = v0;
            *(float4*)(gp + 4) = v1;
        }
    }
}

// ---------------------------------------------------------------------------
// Phase 3: persistent recurrent kernel (flag-based sync, per direction)
// ---------------------------------------------------------------------------
__global__ void __launch_bounds__(GT, 1) gru_seq_kernel(
    const float* __restrict__ w_hh,
    const float* __restrict__ b_hh,
    float* __restrict__ out) {

    extern __shared__ float smem[];
    float* wsh  = smem;                 // RPC * HID weights
    float* bsh  = smem + RPC * HID;     // RPC biases
    float* sums = bsh + RPC;            // RPC partial sums

    const int cta  = blockIdx.x;
    const int dir  = cta >> 6;          // 0 = forward, 1 = backward
    const int lcta = cta & 63;
    const int u0   = lcta * UNITS;

    // Load this CTA's 48 w_hh rows into smem.
    // Local row rr -> global row ((rr>>4)<<10) + u0 + (rr&15)  (gate-major).
    for (int i = threadIdx.x; i < RPC * HID; i += GT) {
        int rr = i >> 10;
        int c  = i & (HID - 1);
        int grow = ((rr >> 4) << 10) + u0 + (rr & 15);
        wsh[i] = w_hh[(size_t)grow * HID + c];
    }
    if (threadIdx.x < RPC) {
        int rr = threadIdx.x;
        bsh[rr] = b_hh[((rr >> 4) << 10) + u0 + (rr & 15)];
    }
    __syncthreads();

    const int warp = threadIdx.x >> 5;
    const int lane = threadIdx.x & 31;
    const float* wp = wsh + warp * RPW * HID + lane * 4;

    const volatile int* fl = &g_flags[dir][0];
    volatile int* my_flag  = &g_flags[dir][lcta];

    float hprev = 0.f;                  // held by threads < UNITS only

    for (int s = 0; s <= SEQ; s++) {
        const int t     = dir ? (SEQ - s) : (s - 1);
        const int girow = (s == 0) ? (SEQ + dir) : t;

        // prefetch gi for unit threads (issued before the flag poll)
        float gir = 0.f, giz = 0.f, gin = 0.f;
        if (threadIdx.x < UNITS) {
            const float* gp = g_GI + (size_t)girow * GATES + u0 + threadIdx.x;
            gir = __ldg(gp);
            giz = __ldg(gp + HID);
            gin = __ldg(gp + 2 * HID);
        }

        // wait for all 64 producers of this direction to publish h of step s-1
        if (s > 0) {
            const int need = s - 1;
            bool ok;
            do {
                int a = fl[lane];
                int b = fl[lane + 32];
                ok = (a >= need) && (b >= need);
            } while (!__all_sync(0xffffffffu, ok));
            __threadfence();            // acquire: order h reads after flags
        }

        // load broadcast h (L2: written by other SMs last step)
        const float4* hp = (const float4*)(&g_h[dir][s & 1][0]) + lane;
        float4 h4[8];
        #pragma unroll
        for (int j = 0; j < 8; j++) h4[j] = __ldcg(hp + 32 * j);

        // 6 dot products per warp, lanes over columns
        float acc[RPW] = {0.f, 0.f, 0.f, 0.f, 0.f, 0.f};
        #pragma unroll
        for (int j = 0; j < 8; j++) {
            const float4 hv = h4[j];
            #pragma unroll
            for (int r = 0; r < RPW; r++) {
                const float4 wv = *(const float4*)(wp + r * HID + j * 128);
                acc[r] += hv.x * wv.x;
                acc[r] += hv.y * wv.y;
                acc[r] += hv.z * wv.z;
                acc[r] += hv.w * wv.w;
            }
        }
        #pragma unroll
        for (int r = 0; r < RPW; r++) {
            float v = acc[r];
            v += __shfl_xor_sync(0xffffffffu, v, 16);
            v += __shfl_xor_sync(0xffffffffu, v, 8);
            v += __shfl_xor_sync(0xffffffffu, v, 4);
            v += __shfl_xor_sync(0xffffffffu, v, 2);
            v += __shfl_xor_sync(0xffffffffu, v, 1);
            if (lane == 0) sums[warp * RPW + r] = v;
        }
        __syncthreads();

        if (threadIdx.x < UNITS) {
            const int i = threadIdx.x;
            const int u = u0 + i;
            float rg = 1.f / (1.f + __expf(-(gir + sums[i]      + bsh[i])));
            float zg = 1.f / (1.f + __expf(-(giz + sums[16 + i] + bsh[16 + i])));
            float ng = tanhf(gin + rg * (sums[32 + i] + bsh[32 + i]));
            float hn = (1.f - zg) * ng + zg * hprev;
            hprev = hn;
            __stcg(&g_h[dir][(s + 1) & 1][u], hn);
            if (s >= 1) {
                // hiddens[t] = [hs_f[t] | hs_b[t]], after h_b (1024 floats)
                out[(size_t)HID + (size_t)t * (2 * HID) + dir * HID + u] = hn;
                if (dir == 1 && t == 0) out[u] = hn;   // h_b = hs_b[0]
            }
        }
        __syncthreads();                // all h writes of this CTA done
        if (threadIdx.x == 0) {
            __threadfence();            // publish h before flag
            *my_flag = s;
        }
    }
}

// ---------------------------------------------------------------------------
// launch
// ---------------------------------------------------------------------------
extern "C" void kernel_launch(void* const* d_in, const int* in_sizes, int n_in,
                              void* d_out, int out_size) {
    const void*  tokens = d_in[0];
    const float* emb    = (const float*)d_in[1];
    const float* w_ih   = (const float*)d_in[2];
    const float* w_hh   = (const float*)d_in[3];
    const float* b_ih   = (const float*)d_in[4];
    const float* b_hh   = (const float*)d_in[5];
    float* out = (float*)d_out;

    const int smem_bytes = (RPC * HID + 2 * RPC + 16) * (int)sizeof(float);
    cudaFuncSetAttribute(gru_seq_kernel,
                         cudaFuncAttributeMaxDynamicSharedMemorySize,
                         smem_bytes);

    prep_tokens_kernel<<<8, 512>>>(tokens);

    dim3 ggrid(GATES / BN, (NROWS + BM - 1) / BM);
    gi_gemm_kernel<<<ggrid, 256>>>(emb, w_ih, b_ih);

    gru_seq_kernel<<<NCTA, GT, smem_bytes>>>(w_hh, b_hh, out);
}

// round 5
// speedup vs baseline: 3.5949x; 3.5949x over previous
#include <cuda_runtime.h>
#include <cstdint>

// ---------------------------------------------------------------------------
// EncoderGRU: bidirectional GRU, SEQ=4096, HIDDEN=EMBED=1024.
//
//   Phase 1: prep tokens (+ zero h ring buffers, reset step counters).
//   Phase 2: GI[t] = w_ih @ emb[tok[t]] + b_ih  -- fp32 SIMT GEMM (4098x3072x1024)
//   Phase 3: persistent kernel, 128 CTAs (64 fwd / 64 bwd), each CTA owns 16
//            hidden units (48 w_hh rows in smem).
//            Sync protocol (round-2-proven semantics):
//              producer: gates -> stcg h -> __syncthreads (CTA visibility)
//                        -> thread0 fence + REDG counter (cumulative release)
//              consumer: EVERY thread polls the counter itself (broadcast
//                        sector, nanosleep backoff) + own threadfence before
//                        loading h. No cross-warp handoff of global data.
// ---------------------------------------------------------------------------

#define VOCAB   50257
#define HID     1024
#define SEQ     4096
#define NROWS   (SEQ + 2)       // 4098: +SOS row, +EOS row
#define GATES   3072

#define NCTA    128             // persistent grid (1 CTA/SM)
#define UNITS   16              // hidden units per CTA (64 CTAs/dir * 16 = 1024)
#define RPC     48              // weight rows per CTA (3 gates * 16 units)
#define GT      256             // threads in recurrent kernel
#define RPW     6               // rows per warp (8 warps * 6 = 48)

// ---- global scratch (allocation-free: __device__ globals) ----
__device__ __align__(16) int   g_tokens[NROWS];
__device__ __align__(16) float g_GI[(size_t)NROWS * GATES];     // ~50 MB
__device__ __align__(16) float g_h[2][2][HID];                  // [dir][buf][unit]
__device__ __align__(128) int  g_cnt[2];                        // per-dir step counter

__device__ __forceinline__ int ldcg_int(const int* p) {
    int v;
    asm volatile("ld.global.cg.b32 %0, [%1];" : "=r"(v) : "l"(p));
    return v;
}

// ---------------------------------------------------------------------------
// Phase 1: token prep + dtype detection + state reset (graph-replay safe)
// ---------------------------------------------------------------------------
__global__ void prep_tokens_kernel(const void* __restrict__ tok_raw) {
    __shared__ int mode64;
    if (threadIdx.x == 0) {
        // Genuine int64 tokens: every value < VOCAB (high word 0).
        // int32 data misread as int64: some 64-bit word >= VOCAB w.h.p.
        const unsigned long long* p = (const unsigned long long*)tok_raw;
        int m = 1;
        #pragma unroll
        for (int i = 0; i < 8; i++)
            if (p[i] >= (unsigned long long)VOCAB) m = 0;
        mode64 = m;
    }
    __syncthreads();
    int idx    = blockIdx.x * blockDim.x + threadIdx.x;
    int stride = blockDim.x * gridDim.x;
    for (int i = idx; i < SEQ; i += stride) {
        int t = mode64 ? (int)((const long long*)tok_raw)[i]
                       : ((const int*)tok_raw)[i];
        g_tokens[i] = t;
    }
    // reset recurrent state (fresh every launch / graph replay)
    if (idx < 2 * 2 * HID) ((float*)g_h)[idx] = 0.f;
    if (idx < 2)           g_cnt[idx] = 0;
    if (blockIdx.x == 0 && threadIdx.x == 0) {
        g_tokens[SEQ]     = 0;  // SOS
        g_tokens[SEQ + 1] = 1;  // EOS
    }
}

// ---------------------------------------------------------------------------
// Phase 2: GI GEMM.  C[m][n] = sum_k emb[tok[m]][k] * w_ih[n][k] + b_ih[n]
// BM=BN=128, BK=8, 256 threads, 8x8 microtile per thread.
// ---------------------------------------------------------------------------
#define BM 128
#define BN 128
#define BK 8

__global__ void __launch_bounds__(256) gi_gemm_kernel(
    const float* __restrict__ emb,
    const float* __restrict__ w_ih,
    const float* __restrict__ b_ih) {

    __shared__ float As[BK][BM];
    __shared__ float Bs[BK][BN];

    const int tid  = threadIdx.x;
    const int m0   = blockIdx.y * BM;
    const int n0   = blockIdx.x * BN;
    const int lrow = tid >> 1;          // 0..127
    const int lk   = (tid & 1) * 4;     // 0 or 4
    const int tx   = tid & 15;
    const int ty   = tid >> 4;

    const int m = m0 + lrow;
    const float* arow_ptr = nullptr;
    if (m < NROWS) arow_ptr = emb + (size_t)g_tokens[m] * HID;
    const float* brow_ptr = w_ih + (size_t)(n0 + lrow) * HID;

    float acc[8][8];
    #pragma unroll
    for (int i = 0; i < 8; i++)
        #pragma unroll
        for (int j = 0; j < 8; j++) acc[i][j] = 0.f;

    for (int k0 = 0; k0 < HID; k0 += BK) {
        float4 a4 = make_float4(0.f, 0.f, 0.f, 0.f);
        if (arow_ptr) a4 = *(const float4*)(arow_ptr + k0 + lk);
        float4 b4 = *(const float4*)(brow_ptr + k0 + lk);
        As[lk + 0][lrow] = a4.x; As[lk + 1][lrow] = a4.y;
        As[lk + 2][lrow] = a4.z; As[lk + 3][lrow] = a4.w;
        Bs[lk + 0][lrow] = b4.x; Bs[lk + 1][lrow] = b4.y;
        Bs[lk + 2][lrow] = b4.z; Bs[lk + 3][lrow] = b4.w;
        __syncthreads();

        #pragma unroll
        for (int kk = 0; kk < BK; kk++) {
            float ra[8], rb[8];
            *(float4*)&ra[0] = *(const float4*)&As[kk][ty * 8];
            *(float4*)&ra[4] = *(const float4*)&As[kk][ty * 8 + 4];
            *(float4*)&rb[0] = *(const float4*)&Bs[kk][tx * 8];
            *(float4*)&rb[4] = *(const float4*)&Bs[kk][tx * 8 + 4];
            #pragma unroll
            for (int i = 0; i < 8; i++)
                #pragma unroll
                for (int j = 0; j < 8; j++)
                    acc[i][j] += ra[i] * rb[j];
        }
        __syncthreads();
    }

    float bias[8];
    *(float4*)&bias[0] = *(const float4*)(b_ih + n0 + tx * 8);
    *(float4*)&bias[4] = *(const float4*)(b_ih + n0 + tx * 8 + 4);

    #pragma unroll
    for (int i = 0; i < 8; i++) {
        int mm = m0 + ty * 8 + i;
        if (mm < NROWS) {
            float* gp = g_GI + (size_t)mm * GATES + n0 + tx * 8;
            float4 v0 = make_float4(acc[i][0] + bias[0], acc[i][1] + bias[1],
                                    acc[i][2] + bias[2], acc[i][3] + bias[3]);
            float4 v1 = make_float4(acc[i][4] + bias[4], acc[i][5] + bias[5],
                                    acc[i][6] + bias[6], acc[i][7] + bias[7]);
            *(float4*)gp       = v0;
            *(float4*)(gp + 4) = v1;
        }
    }
}

// ---------------------------------------------------------------------------
// Phase 3: persistent recurrent kernel
// ---------------------------------------------------------------------------
__global__ void __launch_bounds__(GT, 1) gru_seq_kernel(
    const float* __restrict__ w_hh,
    const float* __restrict__ b_hh,
    float* __restrict__ out) {

    extern __shared__ float smem[];
    float* wsh  = smem;                 // RPC * HID weights
    float* bsh  = smem + RPC * HID;     // RPC biases
    float* sums = bsh + RPC;            // RPC partial sums

    const int cta  = blockIdx.x;
    const int dir  = cta >> 6;          // 0 = forward, 1 = backward
    const int lcta = cta & 63;
    const int u0   = lcta * UNITS;

    // Load this CTA's 48 w_hh rows into smem.
    // Local row rr -> global row ((rr>>4)<<10) + u0 + (rr&15)  (gate-major).
    for (int i = threadIdx.x; i < RPC * HID; i += GT) {
        int rr = i >> 10;
        int c  = i & (HID - 1);
        int grow = ((rr >> 4) << 10) + u0 + (rr & 15);
        wsh[i] = w_hh[(size_t)grow * HID + c];
    }
    if (threadIdx.x < RPC) {
        int rr = threadIdx.x;
        bsh[rr] = b_hh[((rr >> 4) << 10) + u0 + (rr & 15)];
    }
    __syncthreads();

    const int warp = threadIdx.x >> 5;
    const int lane = threadIdx.x & 31;
    const float* wp = wsh + warp * RPW * HID + lane * 4;
    const int* cnt_p = &g_cnt[dir];

    float hprev = 0.f;                  // held by threads < UNITS only

    for (int s = 0; s <= SEQ; s++) {
        const int t     = dir ? (SEQ - s) : (s - 1);
        const int girow = (s == 0) ? (SEQ + dir) : t;

        // gi prefetch (independent of h; overlaps the poll below)
        float gir = 0.f, giz = 0.f, gin = 0.f;
        if (threadIdx.x < UNITS) {
            const float* gp = g_GI + (size_t)girow * GATES + u0 + threadIdx.x;
            gir = __ldg(gp);
            giz = __ldg(gp + HID);
            gin = __ldg(gp + 2 * HID);
        }

        // Wait until all 64 CTAs of this direction finished step s-1.
        // EVERY thread observes the counter itself (broadcast 4B sector) and
        // fences itself -- the round-2-proven acquire pattern. nanosleep
        // backoff keeps the hot sector below its L2 service capacity.
        if (s > 0) {
            const int need = s << 6;    // 64 * s
            if (ldcg_int(cnt_p) < need) {
                do { __nanosleep(60); } while (ldcg_int(cnt_p) < need);
            }
            __threadfence();            // acquire (per-thread)
        }

        // load broadcast h (L2: written by other SMs last step)
        const float4* hp = (const float4*)(&g_h[dir][s & 1][0]) + lane;
        float4 h4[8];
        #pragma unroll
        for (int j = 0; j < 8; j++) h4[j] = __ldcg(hp + 32 * j);

        // 6 dot products per warp, lanes stride columns by 4
        float acc[RPW] = {0.f, 0.f, 0.f, 0.f, 0.f, 0.f};
        #pragma unroll
        for (int j = 0; j < 8; j++) {
            const float4 hv = h4[j];
            #pragma unroll
            for (int r = 0; r < RPW; r++) {
                const float4 wv = *(const float4*)(wp + r * HID + j * 128);
                acc[r] += hv.x * wv.x;
                acc[r] += hv.y * wv.y;
                acc[r] += hv.z * wv.z;
                acc[r] += hv.w * wv.w;
            }
        }
        #pragma unroll
        for (int r = 0; r < RPW; r++) {
            float v = acc[r];
            v += __shfl_xor_sync(0xffffffffu, v, 16);
            v += __shfl_xor_sync(0xffffffffu, v, 8);
            v += __shfl_xor_sync(0xffffffffu, v, 4);
            v += __shfl_xor_sync(0xffffffffu, v, 2);
            v += __shfl_xor_sync(0xffffffffu, v, 1);
            if (lane == 0) sums[warp * RPW + r] = v;
        }
        __syncthreads();                // sums ready

        if (threadIdx.x < UNITS) {
            const int i = threadIdx.x;
            const int u = u0 + i;
            float rg = 1.f / (1.f + __expf(-(gir + sums[i]      + bsh[i])));
            float zg = 1.f / (1.f + __expf(-(giz + sums[16 + i] + bsh[16 + i])));
            float ng = tanhf(gin + rg * (sums[32 + i] + bsh[32 + i]));
            float hn = (1.f - zg) * ng + zg * hprev;
            hprev = hn;
            __stcg(&g_h[dir][(s + 1) & 1][u], hn);
            if (s >= 1) {
                // hiddens[t] = [hs_f[t] | hs_b[t]], after h_b (1024 floats)
                out[(size_t)HID + (size_t)t * (2 * HID) + dir * HID + u] = hn;
                if (dir == 1 && t == 0) out[u] = hn;   // h_b = hs_b[0]
            }
        }
        __syncthreads();                // h writes CTA-visible (r2 pattern)
        if (threadIdx.x == 0) {
            __threadfence();            // cumulative release: h before counter
            atomicAdd(&g_cnt[dir], 1);  // REDG (result unused)
        }
    }
}

// ---------------------------------------------------------------------------
// launch
// ---------------------------------------------------------------------------
extern "C" void kernel_launch(void* const* d_in, const int* in_sizes, int n_in,
                              void* d_out, int out_size) {
    const void*  tokens = d_in[0];
    const float* emb    = (const float*)d_in[1];
    const float* w_ih   = (const float*)d_in[2];
    const float* w_hh   = (const float*)d_in[3];
    const float* b_ih   = (const float*)d_in[4];
    const float* b_hh   = (const float*)d_in[5];
    float* out = (float*)d_out;

    const int smem_bytes = (RPC * HID + 2 * RPC + 16) * (int)sizeof(float);
    cudaFuncSetAttribute(gru_seq_kernel,
                         cudaFuncAttributeMaxDynamicSharedMemorySize,
                         smem_bytes);

    prep_tokens_kernel<<<8, 512>>>(tokens);

    dim3 ggrid(GATES / BN, (NROWS + BM - 1) / BM);
    gi_gemm_kernel<<<ggrid, 256>>>(emb, w_ih, b_ih);

    gru_seq_kernel<<<NCTA, GT, smem_bytes>>>(w_hh, b_hh, out);
}

// round 7
// speedup vs baseline: 3.7994x; 1.0569x over previous
#include <cuda_runtime.h>
#include <cstdint>

// ---------------------------------------------------------------------------
// EncoderGRU: bidirectional GRU, SEQ=4096, HIDDEN=EMBED=1024.
//
//   Phase 1 (fused into GEMM): token dtype detection + inline token reads +
//            state reset (h ring, step counters) by block (0,0).
//   Phase 2: GI[t] = w_ih @ emb[tok[t]] + b_ih  -- fp32 SIMT GEMM (4098x3072x1024)
//   Phase 3: persistent kernel, 128 CTAs (64 fwd / 64 bwd), each CTA owns 16
//            hidden units (48 w_hh rows in smem).
//            Sync protocol: EXACTLY round-5 (proven): producer gates -> stcg h
//            -> __syncthreads -> thread0 fence + REDG counter; consumer: every
//            thread first-check + nanosleep-poll + own threadfence.
//            ONLY change vs r5: each direction's counter on its own 128B line
//            (r5 had both counters in one L2 sector -> 1024 polling warps +
//            releases all queued on one slice).
// ---------------------------------------------------------------------------

#define VOCAB   50257
#define HID     1024
#define SEQ     4096
#define NROWS   (SEQ + 2)       // 4098: +SOS row, +EOS row
#define GATES   3072

#define NCTA    128             // persistent grid (1 CTA/SM)
#define UNITS   16              // hidden units per CTA (64 CTAs/dir * 16 = 1024)
#define RPC     48              // weight rows per CTA (3 gates * 16 units)
#define GT      256             // threads in recurrent kernel
#define RPW     6               // rows per warp (8 warps * 6 = 48)

// ---- global scratch (allocation-free: __device__ globals) ----
__device__ __align__(16)  float g_GI[(size_t)NROWS * GATES];    // ~50 MB
__device__ __align__(16)  float g_h[2][2][HID];                 // [dir][buf][unit]
__device__ __align__(128) int   g_cnt[2][32];                   // [dir][pad] one line/dir

__device__ __forceinline__ int ldcg_int(const int* p) {
    int v;
    asm volatile("ld.global.cg.b32 %0, [%1];" : "=r"(v) : "l"(p));
    return v;
}

// ---------------------------------------------------------------------------
// Phase 1+2: GI GEMM with inline token prep.
// C[m][n] = sum_k emb[tok[m]][k] * w_ih[n][k] + b_ih[n]
// BM=BN=128, BK=8, 256 threads, 8x8 microtile per thread.
// Block (0,0) additionally resets the recurrent state (h ring + counters);
// the gru kernel launches after this one on the same stream, so ordering
// is guaranteed without any extra sync.
// ---------------------------------------------------------------------------
#define BM 128
#define BN 128
#define BK 8

__global__ void __launch_bounds__(256) gi_gemm_kernel(
    const void*  __restrict__ tok_raw,
    const float* __restrict__ emb,
    const float* __restrict__ w_ih,
    const float* __restrict__ b_ih) {

    __shared__ float As[BK][BM];
    __shared__ float Bs[BK][BN];
    __shared__ int   mode64_sh;

    const int tid  = threadIdx.x;
    const int m0   = blockIdx.y * BM;
    const int n0   = blockIdx.x * BN;
    const int lrow = tid >> 1;          // 0..127
    const int lk   = (tid & 1) * 4;     // 0 or 4
    const int tx   = tid & 15;
    const int ty   = tid >> 4;

    // state reset (fresh every launch / graph replay) -- block (0,0) only
    if (blockIdx.x == 0 && blockIdx.y == 0) {
        for (int i = tid; i < 2 * 2 * HID; i += 256) ((float*)g_h)[i] = 0.f;
        if (tid < 64) ((int*)g_cnt)[tid] = 0;
    }

    // token dtype detection (per block; 8 loads, trivial)
    if (tid == 0) {
        // Genuine int64 tokens: every value < VOCAB (high word 0).
        // int32 data misread as int64: some 64-bit word >= VOCAB w.h.p.
        const unsigned long long* p = (const unsigned long long*)tok_raw;
        int m = 1;
        #pragma unroll
        for (int i = 0; i < 8; i++)
            if (p[i] >= (unsigned long long)VOCAB) m = 0;
        mode64_sh = m;
    }
    __syncthreads();
    const int mode64 = mode64_sh;

    // inline token fetch for this block's A row
    const int m = m0 + lrow;
    const float* arow_ptr = nullptr;
    if (m < NROWS) {
        int tok;
        if (m == SEQ)          tok = 0;   // SOS
        else if (m == SEQ + 1) tok = 1;   // EOS
        else tok = mode64 ? (int)((const long long*)tok_raw)[m]
                          : ((const int*)tok_raw)[m];
        arow_ptr = emb + (size_t)tok * HID;
    }
    const float* brow_ptr = w_ih + (size_t)(n0 + lrow) * HID;

    float acc[8][8];
    #pragma unroll
    for (int i = 0; i < 8; i++)
        #pragma unroll
        for (int j = 0; j < 8; j++) acc[i][j] = 0.f;

    for (int k0 = 0; k0 < HID; k0 += BK) {
        float4 a4 = make_float4(0.f, 0.f, 0.f, 0.f);
        if (arow_ptr) a4 = *(const float4*)(arow_ptr + k0 + lk);
        float4 b4 = *(const float4*)(brow_ptr + k0 + lk);
        As[lk + 0][lrow] = a4.x; As[lk + 1][lrow] = a4.y;
        As[lk + 2][lrow] = a4.z; As[lk + 3][lrow] = a4.w;
        Bs[lk + 0][lrow] = b4.x; Bs[lk + 1][lrow] = b4.y;
        Bs[lk + 2][lrow] = b4.z; Bs[lk + 3][lrow] = b4.w;
        __syncthreads();

        #pragma unroll
        for (int kk = 0; kk < BK; kk++) {
            float ra[8], rb[8];
            *(float4*)&ra[0] = *(const float4*)&As[kk][ty * 8];
            *(float4*)&ra[4] = *(const float4*)&As[kk][ty * 8 + 4];
            *(float4*)&rb[0] = *(const float4*)&Bs[kk][tx * 8];
            *(float4*)&rb[4] = *(const float4*)&Bs[kk][tx * 8 + 4];
            #pragma unroll
            for (int i = 0; i < 8; i++)
                #pragma unroll
                for (int j = 0; j < 8; j++)
                    acc[i][j] += ra[i] * rb[j];
        }
        __syncthreads();
    }

    float bias[8];
    *(float4*)&bias[0] = *(const float4*)(b_ih + n0 + tx * 8);
    *(float4*)&bias[4] = *(const float4*)(b_ih + n0 + tx * 8 + 4);

    #pragma unroll
    for (int i = 0; i < 8; i++) {
        int mm = m0 + ty * 8 + i;
        if (mm < NROWS) {
            float* gp = g_GI + (size_t)mm * GATES + n0 + tx * 8;
            float4 v0 = make_float4(acc[i][0] + bias[0], acc[i][1] + bias[1],
                                    acc[i][2] + bias[2], acc[i][3] + bias[3]);
            float4 v1 = make_float4(acc[i][4] + bias[4], acc[i][5] + bias[5],
                                    acc[i][6] + bias[6], acc[i][7] + bias[7]);
            *(float4*)gp       = v0;
            *(float4*)(gp + 4) = v1;
        }
    }
}

// ---------------------------------------------------------------------------
// Phase 3: persistent recurrent kernel -- round-5 code verbatim; the ONLY
// change is the counter address (g_cnt[dir][0], one 128B line per direction).
// ---------------------------------------------------------------------------
__global__ void __launch_bounds__(GT, 1) gru_seq_kernel(
    const float* __restrict__ w_hh,
    const float* __restrict__ b_hh,
    float* __restrict__ out) {

    extern __shared__ float smem[];
    float* wsh  = smem;                 // RPC * HID weights
    float* bsh  = smem + RPC * HID;     // RPC biases
    float* sums = bsh + RPC;            // RPC partial sums

    const int cta  = blockIdx.x;
    const int dir  = cta >> 6;          // 0 = forward, 1 = backward
    const int lcta = cta & 63;
    const int u0   = lcta * UNITS;

    // Load this CTA's 48 w_hh rows into smem.
    // Local row rr -> global row ((rr>>4)<<10) + u0 + (rr&15)  (gate-major).
    for (int i = threadIdx.x; i < RPC * HID; i += GT) {
        int rr = i >> 10;
        int c  = i & (HID - 1);
        int grow = ((rr >> 4) << 10) + u0 + (rr & 15);
        wsh[i] = w_hh[(size_t)grow * HID + c];
    }
    if (threadIdx.x < RPC) {
        int rr = threadIdx.x;
        bsh[rr] = b_hh[((rr >> 4) << 10) + u0 + (rr & 15)];
    }
    __syncthreads();

    const int warp = threadIdx.x >> 5;
    const int lane = threadIdx.x & 31;
    const float* wp = wsh + warp * RPW * HID + lane * 4;
    const int* cnt_p = &g_cnt[dir][0];

    float hprev = 0.f;                  // held by threads < UNITS only

    for (int s = 0; s <= SEQ; s++) {
        const int t     = dir ? (SEQ - s) : (s - 1);
        const int girow = (s == 0) ? (SEQ + dir) : t;

        // gi prefetch (independent of h; overlaps the poll below)
        float gir = 0.f, giz = 0.f, gin = 0.f;
        if (threadIdx.x < UNITS) {
            const float* gp = g_GI + (size_t)girow * GATES + u0 + threadIdx.x;
            gir = __ldg(gp);
            giz = __ldg(gp + HID);
            gin = __ldg(gp + 2 * HID);
        }

        // Wait until all 64 CTAs of this direction finished step s-1.
        // EVERY thread observes the counter itself (broadcast 4B sector) and
        // fences itself -- the round-5-proven acquire pattern. nanosleep
        // backoff keeps the hot sector below its L2 service capacity.
        if (s > 0) {
            const int need = s << 6;    // 64 * s
            if (ldcg_int(cnt_p) < need) {
                do { __nanosleep(60); } while (ldcg_int(cnt_p) < need);
            }
            __threadfence();            // acquire (per-thread)
        }

        // load broadcast h (L2: written by other SMs last step)
        const float4* hp = (const float4*)(&g_h[dir][s & 1][0]) + lane;
        float4 h4[8];
        #pragma unroll
        for (int j = 0; j < 8; j++) h4[j] = __ldcg(hp + 32 * j);

        // 6 dot products per warp, lanes stride columns by 4
        float acc[RPW] = {0.f, 0.f, 0.f, 0.f, 0.f, 0.f};
        #pragma unroll
        for (int j = 0; j < 8; j++) {
            const float4 hv = h4[j];
            #pragma unroll
            for (int r = 0; r < RPW; r++) {
                const float4 wv = *(const float4*)(wp + r * HID + j * 128);
                acc[r] += hv.x * wv.x;
                acc[r] += hv.y * wv.y;
                acc[r] += hv.z * wv.z;
                acc[r] += hv.w * wv.w;
            }
        }
        #pragma unroll
        for (int r = 0; r < RPW; r++) {
            float v = acc[r];
            v += __shfl_xor_sync(0xffffffffu, v, 16);
            v += __shfl_xor_sync(0xffffffffu, v, 8);
            v += __shfl_xor_sync(0xffffffffu, v, 4);
            v += __shfl_xor_sync(0xffffffffu, v, 2);
            v += __shfl_xor_sync(0xffffffffu, v, 1);
            if (lane == 0) sums[warp * RPW + r] = v;
        }
        __syncthreads();                // sums ready

        if (threadIdx.x < UNITS) {
            const int i = threadIdx.x;
            const int u = u0 + i;
            float rg = 1.f / (1.f + __expf(-(gir + sums[i]      + bsh[i])));
            float zg = 1.f / (1.f + __expf(-(giz + sums[16 + i] + bsh[16 + i])));
            float ng = tanhf(gin + rg * (sums[32 + i] + bsh[32 + i]));
            float hn = (1.f - zg) * ng + zg * hprev;
            hprev = hn;
            __stcg(&g_h[dir][(s + 1) & 1][u], hn);
            if (s >= 1) {
                // hiddens[t] = [hs_f[t] | hs_b[t]], after h_b (1024 floats)
                out[(size_t)HID + (size_t)t * (2 * HID) + dir * HID + u] = hn;
                if (dir == 1 && t == 0) out[u] = hn;   // h_b = hs_b[0]
            }
        }
        __syncthreads();                // h writes CTA-visible (r5 pattern)
        if (threadIdx.x == 0) {
            __threadfence();            // cumulative release: h before counter
            atomicAdd(&g_cnt[dir][0], 1);  // REDG (result unused)
        }
    }
}

// ---------------------------------------------------------------------------
// launch
// ---------------------------------------------------------------------------
extern "C" void kernel_launch(void* const* d_in, const int* in_sizes, int n_in,
                              void* d_out, int out_size) {
    const void*  tokens = d_in[0];
    const float* emb    = (const float*)d_in[1];
    const float* w_ih   = (const float*)d_in[2];
    const float* w_hh   = (const float*)d_in[3];
    const float* b_ih   = (const float*)d_in[4];
    const float* b_hh   = (const float*)d_in[5];
    float* out = (float*)d_out;

    const int smem_bytes = (RPC * HID + 2 * RPC + 16) * (int)sizeof(float);
    cudaFuncSetAttribute(gru_seq_kernel,
                         cudaFuncAttributeMaxDynamicSharedMemorySize,
                         smem_bytes);

    dim3 ggrid(GATES / BN, (NROWS + BM - 1) / BM);
    gi_gemm_kernel<<<ggrid, 256>>>(tokens, emb, w_ih, b_ih);

    gru_seq_kernel<<<NCTA, GT, smem_bytes>>>(w_hh, b_hh, out);
}